// round 1
// baseline (speedup 1.0000x reference)
#include <cuda_runtime.h>
#include <cuda_bf16.h>
#include <math.h>

#define B_    512
#define D_    512
#define C_    100000
#define KNN   200
#define NCLS  1000
#define GCONST 0.005f   // 1/(2*sigma^2), sigma=10

// ---------------- scratch (static device globals; no allocation) -------------
__device__ float g_c2[C_];                          // 400 KB
__device__ float g_keys[(size_t)B_ * C_];           // 204.8 MB
__device__ int   g_nbr[B_ * KNN];                   // 400 KB

// ---------------- kernel 1: centre squared norms ------------------------------
__global__ void c2_kernel(const float* __restrict__ centres) {
    int warp = (blockIdx.x * blockDim.x + threadIdx.x) >> 5;
    int lane = threadIdx.x & 31;
    if (warp >= C_) return;
    const float4* row = (const float4*)(centres + (size_t)warp * D_);
    float s = 0.f;
#pragma unroll 4
    for (int j = lane; j < D_ / 4; j += 32) {
        float4 v = row[j];
        s += v.x * v.x + v.y * v.y + v.z * v.z + v.w * v.w;
    }
#pragma unroll
    for (int o = 16; o; o >>= 1) s += __shfl_xor_sync(0xffffffffu, s, o);
    if (lane == 0) g_c2[warp] = s;
}

// ---------------- kernel 2: fp32 GEMM, key = c2 - 2*dot ----------------------
#define BM 128
#define BN 128
#define BK 16
__global__ __launch_bounds__(256) void gemm_kernel(const float* __restrict__ A,
                                                   const float* __restrict__ Bm) {
    __shared__ float As[BK][BM];
    __shared__ float Bs[BK][BN];
    const int m0 = blockIdx.y * BM;
    const int c0 = blockIdx.x * BN;
    const int t  = threadIdx.x;
    const int tx = t & 15;        // 0..15 -> 8 cols each
    const int ty = t >> 4;        // 0..15 -> 8 rows each

    float acc[8][8];
#pragma unroll
    for (int i = 0; i < 8; i++)
#pragma unroll
        for (int j = 0; j < 8; j++) acc[i][j] = 0.f;

    for (int kt = 0; kt < D_; kt += BK) {
        __syncthreads();
#pragma unroll
        for (int l = 0; l < 2; l++) {
            int idx = t + l * 256;          // 0..511 -> 512 float4 per operand
            int r   = idx >> 2;             // 0..127
            int c4  = (idx & 3) * 4;        // 0,4,8,12
            float4 av = *(const float4*)(A + (size_t)(m0 + r) * D_ + kt + c4);
            As[c4 + 0][r] = av.x; As[c4 + 1][r] = av.y;
            As[c4 + 2][r] = av.z; As[c4 + 3][r] = av.w;
            int gc = c0 + r;
            float4 bv = make_float4(0.f, 0.f, 0.f, 0.f);
            if (gc < C_) bv = *(const float4*)(Bm + (size_t)gc * D_ + kt + c4);
            Bs[c4 + 0][r] = bv.x; Bs[c4 + 1][r] = bv.y;
            Bs[c4 + 2][r] = bv.z; Bs[c4 + 3][r] = bv.w;
        }
        __syncthreads();
#pragma unroll
        for (int k = 0; k < BK; k++) {
            float a[8], b[8];
#pragma unroll
            for (int i = 0; i < 8; i++) a[i] = As[k][ty * 8 + i];
#pragma unroll
            for (int j = 0; j < 8; j++) b[j] = Bs[k][tx * 8 + j];
#pragma unroll
            for (int i = 0; i < 8; i++)
#pragma unroll
                for (int j = 0; j < 8; j++) acc[i][j] += a[i] * b[j];
        }
    }

    // epilogue: key = c2[c] - 2*dot
    float c2v[8];
#pragma unroll
    for (int j = 0; j < 8; j++) {
        int c = c0 + tx * 8 + j;
        c2v[j] = (c < C_) ? g_c2[c] : 0.f;
    }
#pragma unroll
    for (int i = 0; i < 8; i++) {
        int m = m0 + ty * 8 + i;
        float* dst = g_keys + (size_t)m * C_;
#pragma unroll
        for (int j = 0; j < 8; j++) {
            int c = c0 + tx * 8 + j;
            if (c < C_) dst[c] = c2v[j] - 2.f * acc[i][j];
        }
    }
}

// ---------------- kernel 3: per-row radix select (200 smallest) --------------
__device__ __forceinline__ unsigned f2ord(float f) {
    unsigned b = __float_as_uint(f);
    return (b & 0x80000000u) ? ~b : (b ^ 0x80000000u);
}

__global__ __launch_bounds__(512) void select_kernel() {
    const int row = blockIdx.x;
    const float* keys = g_keys + (size_t)row * C_;
    __shared__ unsigned hist[256];
    __shared__ unsigned sh_prefix;
    __shared__ int sh_k, sh_cntlow, sh_tiecnt;
    __shared__ int tieIdx[256];
    const int t = threadIdx.x;
    const int lane = t & 31;
    if (t == 0) { sh_prefix = 0; sh_k = KNN; sh_cntlow = 0; sh_tiecnt = 0; }
    __syncthreads();

    for (int shift = 24; shift >= 0; shift -= 8) {
        if (t < 256) hist[t] = 0;
        __syncthreads();
        unsigned prefix = sh_prefix;
        for (int i = t; i < ((C_ + 511) & ~511); i += 512) {
            bool valid = (i < C_);
            unsigned u = valid ? f2ord(keys[i]) : 0u;
            bool m = valid && (shift == 24 || (u >> (shift + 8)) == prefix);
            unsigned bucket = (u >> shift) & 255u;
            unsigned act = __ballot_sync(0xffffffffu, m);
            if (m) {  // warp-aggregated histogram update
                unsigned peers = __match_any_sync(act, bucket);
                if (lane == (__ffs(peers) - 1))
                    atomicAdd(&hist[bucket], (unsigned)__popc(peers));
            }
        }
        __syncthreads();
        if (t == 0) {
            int k = sh_k;
            unsigned cum = 0; int j = 0;
            for (; j < 256; j++) {
                unsigned h = hist[j];
                if (cum + h >= (unsigned)k) { sh_k = k - (int)cum; break; }
                cum += h;
            }
            sh_prefix = (prefix << 8) | (unsigned)j;
        }
        __syncthreads();
    }

    const unsigned T = sh_prefix;   // exact u32 key at rank 200
    const int need  = sh_k;         // how many ties at T to take (lowest index)
    int* nbr = g_nbr + row * KNN;

    for (int i = t; i < C_; i += 512) {
        unsigned u = f2ord(keys[i]);
        if (u < T) {
            int pos = atomicAdd(&sh_cntlow, 1);
            nbr[pos] = i;
        } else if (u == T) {
            int pos = atomicAdd(&sh_tiecnt, 1);
            if (pos < 256) tieIdx[pos] = i;
        }
    }
    __syncthreads();
    if (t == 0) {
        int low = sh_cntlow;                 // == KNN - need
        int tc  = min(sh_tiecnt, 256);
        int prev = -1;
        for (int s = 0; s < need; s++) {     // pick smallest-index ties (JAX tie order)
            int best = 0x7fffffff;
            for (int q = 0; q < tc; q++) {
                int v = tieIdx[q];
                if (v > prev && v < best) best = v;
            }
            nbr[low + s] = best;
            prev = best;
        }
    }
}

// ---------------- kernel 4: exact d2, gaussian weights, class histogram ------
__global__ __launch_bounds__(256) void final_kernel(const float* __restrict__ features,
                                                    const float* __restrict__ centres,
                                                    const int*   __restrict__ labels,
                                                    const float* __restrict__ weight,
                                                    float* __restrict__ out) {
    const int row = blockIdx.x;
    __shared__ float f[D_];
    __shared__ float p[NCLS];
    __shared__ float red[8];
    const int t = threadIdx.x;
    const int warp = t >> 5, lane = t & 31;

    for (int i = t; i < D_; i += 256) f[i] = features[(size_t)row * D_ + i];
    for (int i = t; i < NCLS; i += 256) p[i] = 0.f;
    __syncthreads();

    for (int n = warp; n < KNN; n += 8) {
        int idx = g_nbr[row * KNN + n];
        const float* c = centres + (size_t)idx * D_;
        float s = 0.f;
#pragma unroll 4
        for (int j = lane; j < D_; j += 32) {
            float diff = f[j] - c[j];
            s += diff * diff;
        }
#pragma unroll
        for (int o = 16; o; o >>= 1) s += __shfl_xor_sync(0xffffffffu, s, o);
        if (lane == 0) {
            float d = expf(-s * GCONST) * expf(weight[idx]);
            atomicAdd(&p[labels[idx]], d);
        }
    }
    __syncthreads();

    float partial = 0.f;
    for (int i = t; i < NCLS; i += 256) {
        float v = p[i];
        if (v == 0.f) v = 1e-10f;
        p[i] = v;
        partial += v;
    }
#pragma unroll
    for (int o = 16; o; o >>= 1) partial += __shfl_xor_sync(0xffffffffu, partial, o);
    if (lane == 0) red[warp] = partial;
    __syncthreads();
    if (t < 32) {
        float v = (t < 8) ? red[t] : 0.f;
#pragma unroll
        for (int o = 4; o; o >>= 1) v += __shfl_xor_sync(0xffffffffu, v, o);
        if (t == 0) red[0] = v;
    }
    __syncthreads();
    const float sum = red[0];
    for (int i = t; i < NCLS; i += 256)
        out[(size_t)row * NCLS + i] = logf(p[i] / sum);
}

// ---------------- launcher ----------------------------------------------------
extern "C" void kernel_launch(void* const* d_in, const int* in_sizes, int n_in,
                              void* d_out, int out_size) {
    const float* features = (const float*)d_in[0];   // [512, 512]
    const float* centres  = (const float*)d_in[1];   // [100000, 512]
    const int*   labels   = (const int*)d_in[2];     // [100000]
    const float* weight   = (const float*)d_in[3];   // [100000]
    float* out = (float*)d_out;                      // [512, 1000]

    c2_kernel<<<(C_ + 7) / 8, 256>>>(centres);

    dim3 gemm_grid((C_ + BN - 1) / BN, B_ / BM);
    gemm_kernel<<<gemm_grid, 256>>>(features, centres);

    select_kernel<<<B_, 512>>>();

    final_kernel<<<B_, 256>>>(features, centres, labels, weight, out);
}

// round 2
// speedup vs baseline: 1.2730x; 1.2730x over previous
#include <cuda_runtime.h>
#include <cuda_bf16.h>
#include <math.h>

#define B_    512
#define D_    512
#define C_    100000
#define KNN   200
#define NCLS  1000
#define GCONST 0.005f   // 1/(2*sigma^2), sigma=10

// ---------------- scratch (static device globals; no allocation) -------------
__device__ float    g_c2[C_];                          // 400 KB
__device__ unsigned g_keys[(size_t)B_ * C_];           // 204.8 MB (order-preserving u32)
__device__ int      g_nbr[B_ * KNN];                   // 400 KB

__device__ __forceinline__ unsigned f2ord(float f) {
    unsigned b = __float_as_uint(f);
    return (b & 0x80000000u) ? ~b : (b ^ 0x80000000u);
}

// ---------------- kernel 1: centre squared norms ------------------------------
__global__ void c2_kernel(const float* __restrict__ centres) {
    int warp = (blockIdx.x * blockDim.x + threadIdx.x) >> 5;
    int lane = threadIdx.x & 31;
    if (warp >= C_) return;
    const float4* row = (const float4*)(centres + (size_t)warp * D_);
    float s = 0.f;
#pragma unroll 4
    for (int j = lane; j < D_ / 4; j += 32) {
        float4 v = row[j];
        s += v.x * v.x + v.y * v.y + v.z * v.z + v.w * v.w;
    }
#pragma unroll
    for (int o = 16; o; o >>= 1) s += __shfl_xor_sync(0xffffffffu, s, o);
    if (lane == 0) g_c2[warp] = s;
}

// ---------------- kernel 2: fp32 GEMM via packed fma.rn.f32x2 ----------------
#define BM 128
#define BN 128
#define BK 16
__global__ __launch_bounds__(256, 2) void gemm_kernel(const float* __restrict__ A,
                                                      const float* __restrict__ Bm) {
    __shared__ float As[2][BK][BM];
    __shared__ float Bs[2][BK][BN];
    const int m0 = blockIdx.y * BM;
    const int c0 = blockIdx.x * BN;
    const int t  = threadIdx.x;
    const int tx = t & 15;        // 0..15 -> 8 output cols each
    const int ty = t >> 4;        // 0..15 -> 8 output rows each

    // per-thread load slots (2 float4 per operand per tile)
    int lr[2], lc4[2];
#pragma unroll
    for (int l = 0; l < 2; l++) {
        int idx = t + l * 256;
        lr[l]  = idx >> 2;
        lc4[l] = (idx & 3) * 4;
    }

    float4 pa[2], pb[2];

    auto load_regs = [&](int kt) {
#pragma unroll
        for (int l = 0; l < 2; l++) {
            pa[l] = *(const float4*)(A + (size_t)(m0 + lr[l]) * D_ + kt + lc4[l]);
            int gc = c0 + lr[l];
            pb[l] = make_float4(0.f, 0.f, 0.f, 0.f);
            if (gc < C_) pb[l] = *(const float4*)(Bm + (size_t)gc * D_ + kt + lc4[l]);
        }
    };
    auto store_smem = [&](int buf) {
#pragma unroll
        for (int l = 0; l < 2; l++) {
            int r = lr[l], c4 = lc4[l];
            As[buf][c4 + 0][r] = pa[l].x; As[buf][c4 + 1][r] = pa[l].y;
            As[buf][c4 + 2][r] = pa[l].z; As[buf][c4 + 3][r] = pa[l].w;
            Bs[buf][c4 + 0][r] = pb[l].x; Bs[buf][c4 + 1][r] = pb[l].y;
            Bs[buf][c4 + 2][r] = pb[l].z; Bs[buf][c4 + 3][r] = pb[l].w;
        }
    };

    unsigned long long acc[8][4];   // 8 rows x 4 col-pairs, packed f32x2
#pragma unroll
    for (int i = 0; i < 8; i++)
#pragma unroll
        for (int j = 0; j < 4; j++) acc[i][j] = 0ull;

    load_regs(0);
    store_smem(0);
    __syncthreads();

    int cur = 0;
    for (int kt = 0; kt < D_; kt += BK) {
        const bool more = (kt + BK < D_);
        if (more) load_regs(kt + BK);

#pragma unroll
        for (int k = 0; k < BK; k++) {
            unsigned long long bb[4];
#pragma unroll
            for (int j = 0; j < 4; j++)
                bb[j] = *(const unsigned long long*)&Bs[cur][k][tx * 8 + j * 2];
#pragma unroll
            for (int i2 = 0; i2 < 4; i2++) {
                float2 a2 = *(const float2*)&As[cur][k][ty * 8 + i2 * 2];
                unsigned ax = __float_as_uint(a2.x);
                unsigned ay = __float_as_uint(a2.y);
                unsigned long long aa0, aa1;
                asm("mov.b64 %0, {%1, %1};" : "=l"(aa0) : "r"(ax));
                asm("mov.b64 %0, {%1, %1};" : "=l"(aa1) : "r"(ay));
#pragma unroll
                for (int j = 0; j < 4; j++) {
                    asm("fma.rn.f32x2 %0, %1, %2, %0;"
                        : "+l"(acc[i2 * 2 + 0][j]) : "l"(aa0), "l"(bb[j]));
                    asm("fma.rn.f32x2 %0, %1, %2, %0;"
                        : "+l"(acc[i2 * 2 + 1][j]) : "l"(aa1), "l"(bb[j]));
                }
            }
        }
        if (more) store_smem(cur ^ 1);
        __syncthreads();
        cur ^= 1;
    }

    // epilogue: key = f2ord(c2[c] - 2*dot)
    float c2v[8];
#pragma unroll
    for (int j = 0; j < 8; j++) {
        int c = c0 + tx * 8 + j;
        c2v[j] = (c < C_) ? g_c2[c] : 0.f;
    }
#pragma unroll
    for (int i = 0; i < 8; i++) {
        int m = m0 + ty * 8 + i;
        unsigned* dst = g_keys + (size_t)m * C_;
#pragma unroll
        for (int j = 0; j < 4; j++) {
            float2 d;
            d.x = __uint_as_float((unsigned)(acc[i][j] & 0xffffffffull));
            d.y = __uint_as_float((unsigned)(acc[i][j] >> 32));
            int c = c0 + tx * 8 + j * 2;
            if (c < C_)     dst[c]     = f2ord(c2v[j * 2]     - 2.f * d.x);
            if (c + 1 < C_) dst[c + 1] = f2ord(c2v[j * 2 + 1] - 2.f * d.y);
        }
    }
}

// ---------------- kernel 3: 2-scan bucket select (200 smallest) --------------
#define NBINS 4096
#define CAP   3072
__global__ __launch_bounds__(512) void select_kernel() {
    const int row = blockIdx.x;
    const unsigned* keys = g_keys + (size_t)row * C_;
    __shared__ unsigned hist[NBINS];
    __shared__ unsigned psum[512];
    __shared__ unsigned long long cand[CAP];
    __shared__ unsigned sh_lo;
    __shared__ unsigned long long sh_hi;
    __shared__ int sh_need, sh_base, sh_cnt, sh_nlow, sh_ncand;
    const int t = threadIdx.x, lane = t & 31;
    if (t == 0) {
        sh_lo = 0; sh_hi = 1ull << 32;
        sh_need = KNN; sh_base = 0; sh_nlow = 0; sh_ncand = 0;
    }
    __syncthreads();

    const int shifts[3] = {20, 8, 0};
    const unsigned masks[3] = {0xFFFu, 0xFFFu, 0xFFu};

    for (int lvl = 0; lvl < 3; lvl++) {
        const int shift = shifts[lvl];
        const unsigned mask = masks[lvl];
        for (int i = t; i < NBINS; i += 512) hist[i] = 0;
        __syncthreads();
        const unsigned lo = sh_lo;
        const unsigned long long hi = sh_hi;
        for (int i = t; i < ((C_ + 511) & ~511); i += 512) {
            bool m = (i < C_);
            unsigned u = m ? keys[i] : 0u;
            m = m && (u >= lo) && ((unsigned long long)u < hi);
            unsigned bucket = (u >> shift) & mask;
            unsigned act = __ballot_sync(0xffffffffu, m);
            if (m) {
                unsigned peers = __match_any_sync(act, bucket);
                if (lane == (__ffs(peers) - 1))
                    atomicAdd(&hist[bucket], (unsigned)__popc(peers));
            }
        }
        __syncthreads();
        unsigned s = 0;
#pragma unroll
        for (int j = 0; j < 8; j++) s += hist[t * 8 + j];
        psum[t] = s;
        __syncthreads();
        if (t == 0) {
            int need = sh_need;
            unsigned cum = 0;
            int p = 0;
            for (; p < 511; p++) {
                if (cum + psum[p] >= (unsigned)need) break;
                cum += psum[p];
            }
            int b = p * 8;
            for (;; b++) {
                if (cum + hist[b] >= (unsigned)need) break;
                cum += hist[b];
            }
            sh_need = need - (int)cum;
            sh_base += (int)cum;
            sh_cnt  = (int)hist[b];
            unsigned newlo = sh_lo + ((unsigned)b << shift);
            sh_lo = newlo;
            sh_hi = (unsigned long long)newlo + (1ull << shift);
        }
        __syncthreads();
        if (sh_cnt <= CAP) break;
    }

    // collect pass
    const unsigned lo = sh_lo;
    const unsigned long long hi = sh_hi;
    int* nbr = g_nbr + row * KNN;
    for (int i = t; i < C_; i += 512) {
        unsigned u = keys[i];
        if (u < lo) {
            int pos = atomicAdd(&sh_nlow, 1);
            nbr[pos] = i;
        } else if ((unsigned long long)u < hi) {
            int pos = atomicAdd(&sh_ncand, 1);
            if (pos < CAP) cand[pos] = ((unsigned long long)u << 32) | (unsigned)i;
        }
    }
    __syncthreads();

    // exact rank-select among candidates: take `need` smallest (key, idx) pairs
    const int cnt = min(sh_ncand, CAP);
    const int need = sh_need, base = sh_base;
    for (int c = t; c < cnt; c += 512) {
        unsigned long long v = cand[c];
        int r = 0;
        for (int q = 0; q < cnt; q++) r += (cand[q] < v);
        if (r < need) nbr[base + r] = (int)(v & 0xffffffffull);
    }
}

// ---------------- kernel 4: exact d2, gaussian weights, class histogram ------
__global__ __launch_bounds__(256) void final_kernel(const float* __restrict__ features,
                                                    const float* __restrict__ centres,
                                                    const int*   __restrict__ labels,
                                                    const float* __restrict__ weight,
                                                    float* __restrict__ out) {
    const int row = blockIdx.x;
    __shared__ float f[D_];
    __shared__ float p[NCLS];
    __shared__ float red[8];
    const int t = threadIdx.x;
    const int warp = t >> 5, lane = t & 31;

    for (int i = t; i < D_; i += 256) f[i] = features[(size_t)row * D_ + i];
    for (int i = t; i < NCLS; i += 256) p[i] = 0.f;
    __syncthreads();

    for (int n = warp; n < KNN; n += 8) {
        int idx = g_nbr[row * KNN + n];
        const float* c = centres + (size_t)idx * D_;
        float s = 0.f;
#pragma unroll 4
        for (int j = lane; j < D_; j += 32) {
            float diff = f[j] - c[j];
            s += diff * diff;
        }
#pragma unroll
        for (int o = 16; o; o >>= 1) s += __shfl_xor_sync(0xffffffffu, s, o);
        if (lane == 0) {
            float d = expf(-s * GCONST) * expf(weight[idx]);
            atomicAdd(&p[labels[idx]], d);
        }
    }
    __syncthreads();

    float partial = 0.f;
    for (int i = t; i < NCLS; i += 256) {
        float v = p[i];
        if (v == 0.f) v = 1e-10f;
        p[i] = v;
        partial += v;
    }
#pragma unroll
    for (int o = 16; o; o >>= 1) partial += __shfl_xor_sync(0xffffffffu, partial, o);
    if (lane == 0) red[warp] = partial;
    __syncthreads();
    if (t < 32) {
        float v = (t < 8) ? red[t] : 0.f;
#pragma unroll
        for (int o = 4; o; o >>= 1) v += __shfl_xor_sync(0xffffffffu, v, o);
        if (t == 0) red[0] = v;
    }
    __syncthreads();
    const float sum = red[0];
    for (int i = t; i < NCLS; i += 256)
        out[(size_t)row * NCLS + i] = logf(p[i] / sum);
}

// ---------------- launcher ----------------------------------------------------
extern "C" void kernel_launch(void* const* d_in, const int* in_sizes, int n_in,
                              void* d_out, int out_size) {
    const float* features = (const float*)d_in[0];   // [512, 512]
    const float* centres  = (const float*)d_in[1];   // [100000, 512]
    const int*   labels   = (const int*)d_in[2];     // [100000]
    const float* weight   = (const float*)d_in[3];   // [100000]
    float* out = (float*)d_out;                      // [512, 1000]

    c2_kernel<<<(C_ + 7) / 8, 256>>>(centres);

    dim3 gemm_grid((C_ + BN - 1) / BN, B_ / BM);
    gemm_kernel<<<gemm_grid, 256>>>(features, centres);

    select_kernel<<<B_, 512>>>();

    final_kernel<<<B_, 256>>>(features, centres, labels, weight, out);
}

// round 4
// speedup vs baseline: 3.7024x; 2.9084x over previous
#include <cuda_runtime.h>
#include <cuda_bf16.h>
#include <math.h>
#include <stdint.h>

#define B_    512
#define D_    512
#define C_    100000
#define KNN   200
#define NCLS  1000
#define GCONST 0.005f     // 1/(2*sigma^2), sigma=10
#define MARGIN 2.0f       // candidate margin in d2 units (~27 sigma of bf16 key err)
#define CCAP  1024        // max candidates per row

// ---------------- scratch (static device globals; no allocation) -------------
__device__ float g_c2[C_];
__device__ __align__(128) float g_keys[(size_t)B_ * C_];           // approx d2-f2 keys
__device__ __align__(128) __nv_bfloat16 g_Abf[(size_t)B_ * D_];    // features bf16
__device__ __align__(128) __nv_bfloat16 g_Bbf[(size_t)C_ * D_];    // centres bf16
__device__ int g_cand[(size_t)B_ * CCAP];
__device__ int g_ccnt[B_];

__device__ __forceinline__ unsigned f2ord(float f) {
    unsigned b = __float_as_uint(f);
    return (b & 0x80000000u) ? ~b : (b ^ 0x80000000u);
}
__device__ __forceinline__ float ord2f(unsigned u) {
    return (u & 0x80000000u) ? __uint_as_float(u ^ 0x80000000u)
                             : __uint_as_float(~u);
}

// ---------------- PTX helpers (base PTX only: sm_80-era) ----------------------
__device__ __forceinline__ uint32_t smem_u32(const void* p) {
    uint32_t a;
    asm("{ .reg .u64 t; cvta.to.shared.u64 t, %1; cvt.u32.u64 %0, t; }"
        : "=r"(a) : "l"(p));
    return a;
}
__device__ __forceinline__ void cpa16(uint32_t dst, const void* src, int sz) {
    asm volatile("cp.async.cg.shared.global [%0], [%1], 16, %2;"
                 :: "r"(dst), "l"(src), "r"(sz));
}
__device__ __forceinline__ void cpcommit() { asm volatile("cp.async.commit_group;"); }
template <int N> __device__ __forceinline__ void cpwait() {
    asm volatile("cp.async.wait_group %0;" :: "n"(N));
}
__device__ __forceinline__ void ldsm4(uint32_t* r, uint32_t addr) {
    asm volatile("ldmatrix.sync.aligned.m8n8.x4.shared.b16 {%0,%1,%2,%3}, [%4];"
                 : "=r"(r[0]), "=r"(r[1]), "=r"(r[2]), "=r"(r[3]) : "r"(addr));
}
__device__ __forceinline__ void mma_bf16(float* d, const uint32_t* a,
                                         uint32_t b0, uint32_t b1) {
    asm volatile(
        "mma.sync.aligned.m16n8k16.row.col.f32.bf16.bf16.f32 "
        "{%0,%1,%2,%3}, {%4,%5,%6,%7}, {%8,%9}, {%0,%1,%2,%3};"
        : "+f"(d[0]), "+f"(d[1]), "+f"(d[2]), "+f"(d[3])
        : "r"(a[0]), "r"(a[1]), "r"(a[2]), "r"(a[3]), "r"(b0), "r"(b1));
}

// ---------------- kernel 1a: centres -> bf16 + c2 -----------------------------
__global__ __launch_bounds__(256) void convertB_kernel(const float* __restrict__ centres) {
    const int warp = (blockIdx.x * 256 + threadIdx.x) >> 5;
    const int lane = threadIdx.x & 31;
    if (warp >= C_) return;
    const float4* src = (const float4*)(centres + (size_t)warp * D_);
    __nv_bfloat16* dst = g_Bbf + (size_t)warp * D_;
    float s = 0.f;
#pragma unroll
    for (int k = 0; k < 4; k++) {
        int j = lane + 32 * k;
        float4 v = src[j];
        s += v.x * v.x + v.y * v.y + v.z * v.z + v.w * v.w;
        union { __nv_bfloat16 h[4]; uint2 u; } ph;
        ph.h[0] = __float2bfloat16_rn(v.x); ph.h[1] = __float2bfloat16_rn(v.y);
        ph.h[2] = __float2bfloat16_rn(v.z); ph.h[3] = __float2bfloat16_rn(v.w);
        *(uint2*)(dst + 4 * j) = ph.u;
    }
#pragma unroll
    for (int o = 16; o; o >>= 1) s += __shfl_xor_sync(0xffffffffu, s, o);
    if (lane == 0) g_c2[warp] = s;
}

// ---------------- kernel 1b: features -> bf16 ---------------------------------
__global__ __launch_bounds__(256) void convertA_kernel(const float* __restrict__ feats) {
    const int warp = (blockIdx.x * 256 + threadIdx.x) >> 5;
    const int lane = threadIdx.x & 31;
    if (warp >= B_) return;
    const float4* src = (const float4*)(feats + (size_t)warp * D_);
    __nv_bfloat16* dst = g_Abf + (size_t)warp * D_;
#pragma unroll
    for (int k = 0; k < 4; k++) {
        int j = lane + 32 * k;
        float4 v = src[j];
        union { __nv_bfloat16 h[4]; uint2 u; } ph;
        ph.h[0] = __float2bfloat16_rn(v.x); ph.h[1] = __float2bfloat16_rn(v.y);
        ph.h[2] = __float2bfloat16_rn(v.z); ph.h[3] = __float2bfloat16_rn(v.w);
        *(uint2*)(dst + 4 * j) = ph.u;
    }
}

// ---------------- kernel 2: bf16 HMMA GEMM, keys = c2 - 2*dot -----------------
// BM=128, BN=128, BK=64, 3-stage cp.async pipeline, 8 warps (4m x 2n), warp 32x64
#define GSTAGE_BYTES 32768
#define GSMEM (1024 + 3 * GSTAGE_BYTES)
__global__ void __launch_bounds__(256, 2) gemm_kernel() {
    extern __shared__ char smem[];
    float* c2s = (float*)smem;
    const uint32_t sb = smem_u32(smem);
    const int t = threadIdx.x;
    const int m0 = blockIdx.y * 128;
    const int c0 = blockIdx.x * 128;
    const int lane = t & 31, wid = t >> 5;
    const int wm = wid & 3, wn = wid >> 2;

    if (t < 128) { int c = c0 + t; c2s[t] = (c < C_) ? g_c2[c] : 0.f; }

    auto load_tile = [&](int kt, int buf) {
        const uint32_t sA = sb + 1024 + buf * GSTAGE_BYTES;
        const uint32_t sB = sA + 16384;
        const __nv_bfloat16* gA = g_Abf + (size_t)m0 * D_ + kt * 64;
        const __nv_bfloat16* gB = g_Bbf + (size_t)c0 * D_ + kt * 64;
#pragma unroll
        for (int i = 0; i < 4; i++) {
            int idx = t + i * 256;          // 1024 16B chunks
            int r = idx >> 3, c = idx & 7;
            cpa16(sA + r * 128 + ((c ^ (r & 7)) << 4),
                  gA + (size_t)r * D_ + c * 8, 16);
        }
#pragma unroll
        for (int i = 0; i < 4; i++) {
            int idx = t + i * 256;
            int r = idx >> 3, c = idx & 7;
            int gr = c0 + r;
            int sz = (gr < C_) ? 16 : 0;
            const __nv_bfloat16* src = gB + (size_t)((gr < C_) ? r : 0) * D_ + c * 8;
            cpa16(sB + r * 128 + ((c ^ (r & 7)) << 4), src, sz);
        }
        cpcommit();
    };

    float acc[2][8][4];
#pragma unroll
    for (int i = 0; i < 2; i++)
#pragma unroll
        for (int j = 0; j < 8; j++)
#pragma unroll
            for (int q = 0; q < 4; q++) acc[i][j][q] = 0.f;

    load_tile(0, 0);
    load_tile(1, 1);

#pragma unroll 1
    for (int kt = 0; kt < 8; kt++) {
        const int buf = kt % 3;
        if (kt == 7) cpwait<0>(); else cpwait<1>();
        __syncthreads();
        if (kt + 2 < 8) load_tile(kt + 2, (kt + 2) % 3);
        const uint32_t sA = sb + 1024 + buf * GSTAGE_BYTES;
        const uint32_t sB = sA + 16384;
#pragma unroll
        for (int kk = 0; kk < 4; kk++) {
            uint32_t a[2][4], b[4][4];
#pragma unroll
            for (int mt = 0; mt < 2; mt++) {
                int r = wm * 32 + mt * 16 + (lane & 15);
                int ch = kk * 2 + (lane >> 4);
                ldsm4(a[mt], sA + r * 128 + ((ch ^ (r & 7)) << 4));
            }
#pragma unroll
            for (int nt = 0; nt < 4; nt++) {
                int r = wn * 64 + nt * 16 + ((lane >> 4) << 3) + (lane & 7);
                int ch = kk * 2 + ((lane >> 3) & 1);
                ldsm4(b[nt], sB + r * 128 + ((ch ^ (r & 7)) << 4));
            }
#pragma unroll
            for (int mt = 0; mt < 2; mt++)
#pragma unroll
                for (int nt = 0; nt < 4; nt++) {
                    mma_bf16(acc[mt][nt * 2],     a[mt], b[nt][0], b[nt][1]);
                    mma_bf16(acc[mt][nt * 2 + 1], a[mt], b[nt][2], b[nt][3]);
                }
        }
    }

    // epilogue: keys = c2 - 2*dot
#pragma unroll
    for (int mt = 0; mt < 2; mt++) {
#pragma unroll
        for (int nt8 = 0; nt8 < 8; nt8++) {
            int lcol = wn * 64 + nt8 * 8 + (lane & 3) * 2;
            int gcol = c0 + lcol;
            if (gcol >= C_) continue;
            int grow = m0 + wm * 32 + mt * 16 + (lane >> 2);
            float2 v0, v1;
            v0.x = c2s[lcol]     - 2.f * acc[mt][nt8][0];
            v0.y = c2s[lcol + 1] - 2.f * acc[mt][nt8][1];
            v1.x = c2s[lcol]     - 2.f * acc[mt][nt8][2];
            v1.y = c2s[lcol + 1] - 2.f * acc[mt][nt8][3];
            *(float2*)(g_keys + (size_t)grow * C_ + gcol) = v0;
            *(float2*)(g_keys + (size_t)(grow + 8) * C_ + gcol) = v1;
        }
    }
}

// ---------------- kernel 3: threshold select -> candidate list ----------------
#define NBINS 4096
__global__ __launch_bounds__(512) void select_kernel() {
    const int row = blockIdx.x;
    const float* keys = g_keys + (size_t)row * C_;
    __shared__ unsigned hist[NBINS];
    __shared__ unsigned psum[512];
    __shared__ unsigned sh_lo;
    __shared__ unsigned long long sh_hi;
    __shared__ int sh_need, sh_done, sh_ncand;
    const int t = threadIdx.x, lane = t & 31;
    if (t == 0) {
        sh_lo = 0; sh_hi = 1ull << 32;
        sh_need = KNN; sh_done = 0; sh_ncand = 0;
    }
    __syncthreads();

    const int shifts[3] = {20, 8, 0};
    const unsigned masks[3] = {0xFFFu, 0xFFFu, 0xFFu};

    for (int lvl = 0; lvl < 3; lvl++) {
        const int shift = shifts[lvl];
        const unsigned mask = masks[lvl];
        for (int i = t; i < NBINS; i += 512) hist[i] = 0;
        __syncthreads();
        const unsigned lo = sh_lo;
        const unsigned long long hi = sh_hi;
        for (int i = t; i < ((C_ + 511) & ~511); i += 512) {
            bool m = (i < C_);
            unsigned u = m ? f2ord(keys[i]) : 0u;
            m = m && (u >= lo) && ((unsigned long long)u < hi);
            unsigned bucket = (u >> shift) & mask;
            unsigned act = __ballot_sync(0xffffffffu, m);
            if (m) {
                unsigned peers = __match_any_sync(act, bucket);
                if (lane == (__ffs(peers) - 1))
                    atomicAdd(&hist[bucket], (unsigned)__popc(peers));
            }
        }
        __syncthreads();
        unsigned s = 0;
#pragma unroll
        for (int j = 0; j < 8; j++) s += hist[t * 8 + j];
        psum[t] = s;
        __syncthreads();
        if (t == 0) {
            int need = sh_need;
            unsigned cum = 0;
            int p = 0;
            for (; p < 511; p++) {
                if (cum + psum[p] >= (unsigned)need) break;
                cum += psum[p];
            }
            int b = p * 8;
            for (;; b++) {
                if (cum + hist[b] >= (unsigned)need) break;
                cum += hist[b];
            }
            sh_need = need - (int)cum;
            unsigned newlo = sh_lo + ((unsigned)b << shift);
            sh_lo = newlo;
            sh_hi = (unsigned long long)newlo + (1ull << shift);
            // stop when bucket is narrow enough in float domain
            float w = ord2f((unsigned)min(sh_hi, 0xFFFFFFFEull)) - ord2f(newlo);
            sh_done = (w <= 0.5f) ? 1 : 0;
        }
        __syncthreads();
        if (sh_done) break;
    }

    // collect: all keys below (bucket lower edge + MARGIN)
    const float T = ord2f(sh_lo) + MARGIN;
    int* cand = g_cand + (size_t)row * CCAP;
    for (int i = t; i < C_; i += 512) {
        if (keys[i] < T) {
            int pos = atomicAdd(&sh_ncand, 1);
            if (pos < CCAP) cand[pos] = i;
        }
    }
    __syncthreads();
    if (t == 0) g_ccnt[row] = min(sh_ncand, CCAP);
}

// ---------------- kernel 4: exact rescore + top-200 + histogram + log --------
__global__ __launch_bounds__(256) void rescore_kernel(const float* __restrict__ features,
                                                      const float* __restrict__ centres,
                                                      const int*   __restrict__ labels,
                                                      const float* __restrict__ weight,
                                                      float* __restrict__ out) {
    const int row = blockIdx.x;
    __shared__ float f[D_];
    __shared__ float p[NCLS];
    __shared__ unsigned long long cnd[CCAP];
    __shared__ float red[8];
    const int t = threadIdx.x;
    const int warp = t >> 5, lane = t & 31;

    for (int i = t; i < D_; i += 256) f[i] = features[(size_t)row * D_ + i];
    for (int i = t; i < NCLS; i += 256) p[i] = 0.f;
    __syncthreads();

    const int cnt = g_ccnt[row];
    const int* cand = g_cand + (size_t)row * CCAP;

    // exact fp32 d2 per candidate (warp per candidate)
    for (int ci = warp; ci < cnt; ci += 8) {
        int idx = cand[ci];
        const float4* c = (const float4*)(centres + (size_t)idx * D_);
        const float4* fs = (const float4*)f;
        float s = 0.f;
#pragma unroll
        for (int k = 0; k < 4; k++) {
            int j = lane + 32 * k;
            float4 cv = c[j];
            float4 fv = fs[j];
            float dx = fv.x - cv.x, dy = fv.y - cv.y;
            float dz = fv.z - cv.z, dw = fv.w - cv.w;
            s += dx * dx + dy * dy + dz * dz + dw * dw;
        }
#pragma unroll
        for (int o = 16; o; o >>= 1) s += __shfl_xor_sync(0xffffffffu, s, o);
        if (lane == 0)
            cnd[ci] = ((unsigned long long)f2ord(s) << 32) | (unsigned)idx;
    }
    __syncthreads();

    // bitonic sort (asc) over padded pow2
    int P = 256;
    while (P < cnt) P <<= 1;
    for (int i = cnt + t; i < P; i += 256) cnd[i] = ~0ull;
    __syncthreads();
    for (int k = 2; k <= P; k <<= 1)
        for (int j = k >> 1; j > 0; j >>= 1) {
            for (int i = t; i < P; i += 256) {
                int ixj = i ^ j;
                if (ixj > i) {
                    unsigned long long a = cnd[i], b = cnd[ixj];
                    bool up = ((i & k) == 0);
                    if ((a > b) == up) { cnd[i] = b; cnd[ixj] = a; }
                }
            }
            __syncthreads();
        }

    // top-200: gaussian weights into class histogram
    const int take = min(KNN, cnt);
    for (int s = t; s < take; s += 256) {
        unsigned long long v = cnd[s];
        int idx = (int)(v & 0xffffffffull);
        float d2 = ord2f((unsigned)(v >> 32));
        float d = expf(-d2 * GCONST) * expf(weight[idx]);
        atomicAdd(&p[labels[idx]], d);
    }
    __syncthreads();

    float partial = 0.f;
    for (int i = t; i < NCLS; i += 256) {
        float v = p[i];
        if (v == 0.f) v = 1e-10f;
        p[i] = v;
        partial += v;
    }
#pragma unroll
    for (int o = 16; o; o >>= 1) partial += __shfl_xor_sync(0xffffffffu, partial, o);
    if (lane == 0) red[warp] = partial;
    __syncthreads();
    if (t < 32) {
        float v = (t < 8) ? red[t] : 0.f;
#pragma unroll
        for (int o = 4; o; o >>= 1) v += __shfl_xor_sync(0xffffffffu, v, o);
        if (t == 0) red[0] = v;
    }
    __syncthreads();
    const float sum = red[0];
    for (int i = t; i < NCLS; i += 256)
        out[(size_t)row * NCLS + i] = logf(p[i] / sum);
}

// ---------------- launcher ----------------------------------------------------
extern "C" void kernel_launch(void* const* d_in, const int* in_sizes, int n_in,
                              void* d_out, int out_size) {
    const float* features = (const float*)d_in[0];   // [512, 512]
    const float* centres  = (const float*)d_in[1];   // [100000, 512]
    const int*   labels   = (const int*)d_in[2];     // [100000]
    const float* weight   = (const float*)d_in[3];   // [100000]
    float* out = (float*)d_out;                      // [512, 1000]

    cudaFuncSetAttribute(gemm_kernel,
                         cudaFuncAttributeMaxDynamicSharedMemorySize, GSMEM);

    convertA_kernel<<<B_ / 8, 256>>>(features);
    convertB_kernel<<<C_ / 8, 256>>>(centres);

    dim3 gg((C_ + 127) / 128, B_ / 128);
    gemm_kernel<<<gg, 256, GSMEM>>>();

    select_kernel<<<B_, 512>>>();

    rescore_kernel<<<B_, 256>>>(features, centres, labels, weight, out);
}

// round 6
// speedup vs baseline: 3.8933x; 1.0516x over previous
#include <cuda_runtime.h>
#include <cuda_bf16.h>
#include <cuda_fp16.h>
#include <math.h>
#include <stdint.h>

#define B_    512
#define D_    512
#define C_    100000
#define KNN   200
#define NCLS  1000
#define GCONST 0.005f     // 1/(2*sigma^2), sigma=10
#define MARGIN 5.0f       // covers 2x(bf16 gemm err + fp16 key quant) + slack
#define CCAP  2048        // max candidates per row

// ---------------- scratch (static device globals; no allocation) -------------
__device__ float g_c2[C_];
__device__ __align__(128) unsigned short g_keys16[(size_t)B_ * C_];  // 102.4 MB
__device__ __align__(128) __nv_bfloat16 g_Abf[(size_t)B_ * D_];
__device__ __align__(128) __nv_bfloat16 g_Bbf[(size_t)C_ * D_];
__device__ int g_cand[(size_t)B_ * CCAP];
__device__ int g_ccnt[B_];

__device__ __forceinline__ unsigned f2ord(float f) {
    unsigned b = __float_as_uint(f);
    return (b & 0x80000000u) ? ~b : (b ^ 0x80000000u);
}
__device__ __forceinline__ float ord2f(unsigned u) {
    return (u & 0x80000000u) ? __uint_as_float(u ^ 0x80000000u)
                             : __uint_as_float(~u);
}
// ordered u16 via fp16
__device__ __forceinline__ unsigned f2ord16(float x) {
    unsigned short h = __half_as_ushort(__float2half_rn(x));
    return (h & 0x8000) ? (unsigned)(unsigned short)~h : (unsigned)(h | 0x8000);
}
__device__ __forceinline__ float ord162f(unsigned u) {
    unsigned short h = (u & 0x8000) ? (unsigned short)(u ^ 0x8000)
                                    : (unsigned short)~u;
    return __half2float(__ushort_as_half(h));
}

// ---------------- PTX helpers (base PTX only) ---------------------------------
__device__ __forceinline__ uint32_t smem_u32(const void* p) {
    uint32_t a;
    asm("{ .reg .u64 t; cvta.to.shared.u64 t, %1; cvt.u32.u64 %0, t; }"
        : "=r"(a) : "l"(p));
    return a;
}
__device__ __forceinline__ void cpa16(uint32_t dst, const void* src, int sz) {
    asm volatile("cp.async.cg.shared.global [%0], [%1], 16, %2;"
                 :: "r"(dst), "l"(src), "r"(sz));
}
__device__ __forceinline__ void cpcommit() { asm volatile("cp.async.commit_group;"); }
template <int N> __device__ __forceinline__ void cpwait() {
    asm volatile("cp.async.wait_group %0;" :: "n"(N));
}
__device__ __forceinline__ void ldsm4(uint32_t* r, uint32_t addr) {
    asm volatile("ldmatrix.sync.aligned.m8n8.x4.shared.b16 {%0,%1,%2,%3}, [%4];"
                 : "=r"(r[0]), "=r"(r[1]), "=r"(r[2]), "=r"(r[3]) : "r"(addr));
}
__device__ __forceinline__ void mma_bf16(float* d, const uint32_t* a,
                                         uint32_t b0, uint32_t b1) {
    asm volatile(
        "mma.sync.aligned.m16n8k16.row.col.f32.bf16.bf16.f32 "
        "{%0,%1,%2,%3}, {%4,%5,%6,%7}, {%8,%9}, {%0,%1,%2,%3};"
        : "+f"(d[0]), "+f"(d[1]), "+f"(d[2]), "+f"(d[3])
        : "r"(a[0]), "r"(a[1]), "r"(a[2]), "r"(a[3]), "r"(b0), "r"(b1));
}

// ---------------- kernel 1a: centres -> bf16 + c2 -----------------------------
__global__ __launch_bounds__(256) void convertB_kernel(const float* __restrict__ centres) {
    const int warp = (blockIdx.x * 256 + threadIdx.x) >> 5;
    const int lane = threadIdx.x & 31;
    if (warp >= C_) return;
    const float4* src = (const float4*)(centres + (size_t)warp * D_);
    __nv_bfloat16* dst = g_Bbf + (size_t)warp * D_;
    float s = 0.f;
#pragma unroll
    for (int k = 0; k < 4; k++) {
        int j = lane + 32 * k;
        float4 v = src[j];
        s += v.x * v.x + v.y * v.y + v.z * v.z + v.w * v.w;
        union { __nv_bfloat16 h[4]; uint2 u; } ph;
        ph.h[0] = __float2bfloat16_rn(v.x); ph.h[1] = __float2bfloat16_rn(v.y);
        ph.h[2] = __float2bfloat16_rn(v.z); ph.h[3] = __float2bfloat16_rn(v.w);
        *(uint2*)(dst + 4 * j) = ph.u;
    }
#pragma unroll
    for (int o = 16; o; o >>= 1) s += __shfl_xor_sync(0xffffffffu, s, o);
    if (lane == 0) g_c2[warp] = s;
}

// ---------------- kernel 1b: features -> bf16 ---------------------------------
__global__ __launch_bounds__(256) void convertA_kernel(const float* __restrict__ feats) {
    const int warp = (blockIdx.x * 256 + threadIdx.x) >> 5;
    const int lane = threadIdx.x & 31;
    if (warp >= B_) return;
    const float4* src = (const float4*)(feats + (size_t)warp * D_);
    __nv_bfloat16* dst = g_Abf + (size_t)warp * D_;
#pragma unroll
    for (int k = 0; k < 4; k++) {
        int j = lane + 32 * k;
        float4 v = src[j];
        union { __nv_bfloat16 h[4]; uint2 u; } ph;
        ph.h[0] = __float2bfloat16_rn(v.x); ph.h[1] = __float2bfloat16_rn(v.y);
        ph.h[2] = __float2bfloat16_rn(v.z); ph.h[3] = __float2bfloat16_rn(v.w);
        *(uint2*)(dst + 4 * j) = ph.u;
    }
}

// ---------------- kernel 2: bf16 HMMA GEMM, u16 keys = ord16(c2 - 2*dot) ------
// grid = (4 m-tiles, 782 c-tiles): x-fast launch order keeps one B column-tile
// hot in L2 across all 4 m-tiles.
#define GSTAGE_BYTES 32768
#define GSMEM (1024 + 3 * GSTAGE_BYTES)
__global__ void __launch_bounds__(256, 2) gemm_kernel() {
    extern __shared__ char smem[];
    float* c2s = (float*)smem;
    const uint32_t sb = smem_u32(smem);
    const int t = threadIdx.x;
    const int m0 = blockIdx.x * 128;
    const int c0 = blockIdx.y * 128;
    const int lane = t & 31, wid = t >> 5;
    const int wm = wid & 3, wn = wid >> 2;

    if (t < 128) { int c = c0 + t; c2s[t] = (c < C_) ? g_c2[c] : 0.f; }

    auto load_tile = [&](int kt, int buf) {
        const uint32_t sA = sb + 1024 + buf * GSTAGE_BYTES;
        const uint32_t sB = sA + 16384;
        const __nv_bfloat16* gA = g_Abf + (size_t)m0 * D_ + kt * 64;
        const __nv_bfloat16* gB = g_Bbf + (size_t)c0 * D_ + kt * 64;
#pragma unroll
        for (int i = 0; i < 4; i++) {
            int idx = t + i * 256;
            int r = idx >> 3, c = idx & 7;
            cpa16(sA + r * 128 + ((c ^ (r & 7)) << 4),
                  gA + (size_t)r * D_ + c * 8, 16);
        }
#pragma unroll
        for (int i = 0; i < 4; i++) {
            int idx = t + i * 256;
            int r = idx >> 3, c = idx & 7;
            int gr = c0 + r;
            int sz = (gr < C_) ? 16 : 0;
            const __nv_bfloat16* src = gB + (size_t)((gr < C_) ? r : 0) * D_ + c * 8;
            cpa16(sB + r * 128 + ((c ^ (r & 7)) << 4), src, sz);
        }
        cpcommit();
    };

    float acc[2][8][4];
#pragma unroll
    for (int i = 0; i < 2; i++)
#pragma unroll
        for (int j = 0; j < 8; j++)
#pragma unroll
            for (int q = 0; q < 4; q++) acc[i][j][q] = 0.f;

    load_tile(0, 0);
    load_tile(1, 1);

#pragma unroll 1
    for (int kt = 0; kt < 8; kt++) {
        const int buf = kt % 3;
        if (kt == 7) cpwait<0>(); else cpwait<1>();
        __syncthreads();
        if (kt + 2 < 8) load_tile(kt + 2, (kt + 2) % 3);
        const uint32_t sA = sb + 1024 + buf * GSTAGE_BYTES;
        const uint32_t sB = sA + 16384;
#pragma unroll
        for (int kk = 0; kk < 4; kk++) {
            uint32_t a[2][4], b[4][4];
#pragma unroll
            for (int mt = 0; mt < 2; mt++) {
                int r = wm * 32 + mt * 16 + (lane & 15);
                int ch = kk * 2 + (lane >> 4);
                ldsm4(a[mt], sA + r * 128 + ((ch ^ (r & 7)) << 4));
            }
#pragma unroll
            for (int nt = 0; nt < 4; nt++) {
                int r = wn * 64 + nt * 16 + ((lane >> 4) << 3) + (lane & 7);
                int ch = kk * 2 + ((lane >> 3) & 1);
                ldsm4(b[nt], sB + r * 128 + ((ch ^ (r & 7)) << 4));
            }
#pragma unroll
            for (int mt = 0; mt < 2; mt++)
#pragma unroll
                for (int nt = 0; nt < 4; nt++) {
                    mma_bf16(acc[mt][nt * 2],     a[mt], b[nt][0], b[nt][1]);
                    mma_bf16(acc[mt][nt * 2 + 1], a[mt], b[nt][2], b[nt][3]);
                }
        }
    }

    // epilogue: u16 ordered keys, 2 cols packed per u32 store
#pragma unroll
    for (int mt = 0; mt < 2; mt++) {
#pragma unroll
        for (int nt8 = 0; nt8 < 8; nt8++) {
            int lcol = wn * 64 + nt8 * 8 + (lane & 3) * 2;
            int gcol = c0 + lcol;
            if (gcol >= C_) continue;
            int grow = m0 + wm * 32 + mt * 16 + (lane >> 2);
            unsigned k0 = f2ord16(c2s[lcol]     - 2.f * acc[mt][nt8][0]);
            unsigned k1 = f2ord16(c2s[lcol + 1] - 2.f * acc[mt][nt8][1]);
            unsigned k2 = f2ord16(c2s[lcol]     - 2.f * acc[mt][nt8][2]);
            unsigned k3 = f2ord16(c2s[lcol + 1] - 2.f * acc[mt][nt8][3]);
            *(unsigned*)(g_keys16 + (size_t)grow * C_ + gcol)       = k0 | (k1 << 16);
            *(unsigned*)(g_keys16 + (size_t)(grow + 8) * C_ + gcol) = k2 | (k3 << 16);
        }
    }
}

// ---------------- kernel 3: 1 hist pass + 1 collect pass ----------------------
#define NBINS 4096
#define NV    (C_ / 8)                     // 12500 uint4 per row
#define NVPAD ((NV + 511) & ~511)          // uniform trip count for collectives
__global__ __launch_bounds__(512) void select_kernel() {
    const int row = blockIdx.x;
    const uint4* keys4 = (const uint4*)(g_keys16 + (size_t)row * C_);
    __shared__ unsigned hist[NBINS];
    __shared__ unsigned psum[512];
    __shared__ unsigned sh_T;
    __shared__ int sh_ncand;
    const int t = threadIdx.x, lane = t & 31;
    if (t == 0) sh_ncand = 0;
    for (int i = t; i < NBINS; i += 512) hist[i] = 0;
    __syncthreads();

    // pass 1: histogram of u16key >> 4 (padded loop: every lane stays in the
    // collective; validity handled via ballot mask)
    for (int i = t; i < NVPAD; i += 512) {
        const bool valid = (i < NV);
        uint4 v = valid ? keys4[i] : make_uint4(0, 0, 0, 0);
        unsigned act = __ballot_sync(0xffffffffu, valid);
        unsigned w[4] = {v.x, v.y, v.z, v.w};
#pragma unroll
        for (int q = 0; q < 4; q++) {
            unsigned b0 = (w[q] & 0xFFFFu) >> 4;
            unsigned b1 = (w[q] >> 20);
            unsigned p0 = __match_any_sync(0xffffffffu, b0) & act;
            if (valid && lane == (__ffs(p0) - 1))
                atomicAdd(&hist[b0], (unsigned)__popc(p0));
            unsigned p1 = __match_any_sync(0xffffffffu, b1) & act;
            if (valid && lane == (__ffs(p1) - 1))
                atomicAdd(&hist[b1], (unsigned)__popc(p1));
        }
    }
    __syncthreads();

    unsigned s = 0;
#pragma unroll
    for (int j = 0; j < 8; j++) s += hist[t * 8 + j];
    psum[t] = s;
    __syncthreads();
    if (t == 0) {
        unsigned cum = 0;
        int p = 0;
        for (; p < 511; p++) {
            if (cum + psum[p] >= (unsigned)KNN) break;
            cum += psum[p];
        }
        int b = p * 8;
        for (;; b++) {
            if (cum + hist[b] >= (unsigned)KNN) break;
            cum += hist[b];
        }
        // threshold: upper edge of bin b plus margin, in ordered-u16 space
        unsigned binUp = (unsigned)((b << 4) | 15);
        float vup = ord162f(binUp);
        unsigned T = f2ord16(vup + MARGIN) + 1;
        if (T > 65535u) T = 65535u;
        sh_T = (T > binUp) ? T : binUp;
    }
    __syncthreads();

    // pass 2: collect all keys <= T (guarded atomics only; divergence-safe)
    const unsigned T = sh_T;
    int* cand = g_cand + (size_t)row * CCAP;
    for (int i = t; i < NV; i += 512) {
        uint4 v = keys4[i];
        unsigned w[4] = {v.x, v.y, v.z, v.w};
        int col = i * 8;
#pragma unroll
        for (int q = 0; q < 4; q++) {
            if ((w[q] & 0xFFFFu) <= T) {
                int pos = atomicAdd(&sh_ncand, 1);
                if (pos < CCAP) cand[pos] = col + q * 2;
            }
            if ((w[q] >> 16) <= T) {
                int pos = atomicAdd(&sh_ncand, 1);
                if (pos < CCAP) cand[pos] = col + q * 2 + 1;
            }
        }
    }
    __syncthreads();
    if (t == 0) g_ccnt[row] = min(sh_ncand, CCAP);
}

// ---------------- kernel 4: exact rescore + top-200 + histogram + log --------
__global__ __launch_bounds__(256) void rescore_kernel(const float* __restrict__ features,
                                                      const float* __restrict__ centres,
                                                      const int*   __restrict__ labels,
                                                      const float* __restrict__ weight,
                                                      float* __restrict__ out) {
    const int row = blockIdx.x;
    __shared__ float f[D_];
    __shared__ float p[NCLS];
    __shared__ unsigned long long cnd[CCAP];
    __shared__ float red[8];
    const int t = threadIdx.x;
    const int warp = t >> 5, lane = t & 31;

    for (int i = t; i < D_; i += 256) f[i] = features[(size_t)row * D_ + i];
    for (int i = t; i < NCLS; i += 256) p[i] = 0.f;
    __syncthreads();

    const int cnt = g_ccnt[row];
    const int* cand = g_cand + (size_t)row * CCAP;

    for (int ci = warp; ci < cnt; ci += 8) {
        int idx = cand[ci];
        const float4* c = (const float4*)(centres + (size_t)idx * D_);
        const float4* fs = (const float4*)f;
        float s = 0.f;
#pragma unroll
        for (int k = 0; k < 4; k++) {
            int j = lane + 32 * k;
            float4 cv = c[j];
            float4 fv = fs[j];
            float dx = fv.x - cv.x, dy = fv.y - cv.y;
            float dz = fv.z - cv.z, dw = fv.w - cv.w;
            s += dx * dx + dy * dy + dz * dz + dw * dw;
        }
#pragma unroll
        for (int o = 16; o; o >>= 1) s += __shfl_xor_sync(0xffffffffu, s, o);
        if (lane == 0)
            cnd[ci] = ((unsigned long long)f2ord(s) << 32) | (unsigned)idx;
    }
    __syncthreads();

    int P = 256;
    while (P < cnt) P <<= 1;
    for (int i = cnt + t; i < P; i += 256) cnd[i] = ~0ull;
    __syncthreads();
    for (int k = 2; k <= P; k <<= 1)
        for (int j = k >> 1; j > 0; j >>= 1) {
            for (int i = t; i < P; i += 256) {
                int ixj = i ^ j;
                if (ixj > i) {
                    unsigned long long a = cnd[i], b = cnd[ixj];
                    bool up = ((i & k) == 0);
                    if ((a > b) == up) { cnd[i] = b; cnd[ixj] = a; }
                }
            }
            __syncthreads();
        }

    const int take = min(KNN, cnt);
    for (int s = t; s < take; s += 256) {
        unsigned long long v = cnd[s];
        int idx = (int)(v & 0xffffffffull);
        float d2 = ord2f((unsigned)(v >> 32));
        float d = expf(-d2 * GCONST) * expf(weight[idx]);
        atomicAdd(&p[labels[idx]], d);
    }
    __syncthreads();

    float partial = 0.f;
    for (int i = t; i < NCLS; i += 256) {
        float v = p[i];
        if (v == 0.f) v = 1e-10f;
        p[i] = v;
        partial += v;
    }
#pragma unroll
    for (int o = 16; o; o >>= 1) partial += __shfl_xor_sync(0xffffffffu, partial, o);
    if (lane == 0) red[warp] = partial;
    __syncthreads();
    if (t < 32) {
        float v = (t < 8) ? red[t] : 0.f;
#pragma unroll
        for (int o = 4; o; o >>= 1) v += __shfl_xor_sync(0xffffffffu, v, o);
        if (t == 0) red[0] = v;
    }
    __syncthreads();
    const float sum = red[0];
    for (int i = t; i < NCLS; i += 256)
        out[(size_t)row * NCLS + i] = logf(p[i] / sum);
}

// ---------------- launcher ----------------------------------------------------
extern "C" void kernel_launch(void* const* d_in, const int* in_sizes, int n_in,
                              void* d_out, int out_size) {
    const float* features = (const float*)d_in[0];   // [512, 512]
    const float* centres  = (const float*)d_in[1];   // [100000, 512]
    const int*   labels   = (const int*)d_in[2];     // [100000]
    const float* weight   = (const float*)d_in[3];   // [100000]
    float* out = (float*)d_out;                      // [512, 1000]

    cudaFuncSetAttribute(gemm_kernel,
                         cudaFuncAttributeMaxDynamicSharedMemorySize, GSMEM);

    convertA_kernel<<<B_ / 8, 256>>>(features);
    convertB_kernel<<<C_ / 8, 256>>>(centres);

    dim3 gg(B_ / 128, (C_ + 127) / 128);   // x = m-tile (fast), y = c-tile
    gemm_kernel<<<gg, 256, GSMEM>>>();

    select_kernel<<<B_, 512>>>();

    rescore_kernel<<<B_, 256>>>(features, centres, labels, weight, out);
}

// round 7
// speedup vs baseline: 6.5154x; 1.6735x over previous
#include <cuda_runtime.h>
#include <cuda_bf16.h>
#include <cuda_fp16.h>
#include <math.h>
#include <stdint.h>

#define B_    512
#define D_    512
#define C_    100000
#define KNN   200
#define NCLS  1000
#define GCONST 0.005f     // 1/(2*sigma^2), sigma=10
#define MARGIN 5.0f       // covers 2x(bf16 gemm err + fp16 key quant) + slack
#define CCAP  2048        // max candidates per row
#define NBLK  (C_ / 8)    // 12500 8-col blocks per row
#define RANK  250         // bmin rank for threshold (>= KNN guaranteed candidates)

// ---------------- scratch (static device globals; no allocation) -------------
__device__ float g_c2[C_];
__device__ __align__(128) unsigned short g_keys16[(size_t)B_ * C_];  // 102.4 MB
__device__ __align__(128) unsigned short g_bmin[(size_t)B_ * NBLK];  // 12.8 MB
__device__ __align__(128) __nv_bfloat16 g_Abf[(size_t)B_ * D_];
__device__ __align__(128) __nv_bfloat16 g_Bbf[(size_t)C_ * D_];
__device__ int g_cand[(size_t)B_ * CCAP];
__device__ int g_ccnt[B_];

__device__ __forceinline__ unsigned f2ord(float f) {
    unsigned b = __float_as_uint(f);
    return (b & 0x80000000u) ? ~b : (b ^ 0x80000000u);
}
__device__ __forceinline__ float ord2f(unsigned u) {
    return (u & 0x80000000u) ? __uint_as_float(u ^ 0x80000000u)
                             : __uint_as_float(~u);
}
// ordered u16 via fp16 (monotonic: x<=y -> ord(x)<=ord(y))
__device__ __forceinline__ unsigned f2ord16(float x) {
    unsigned short h = __half_as_ushort(__float2half_rn(x));
    return (h & 0x8000) ? (unsigned)(unsigned short)~h : (unsigned)(h | 0x8000);
}
__device__ __forceinline__ float ord162f(unsigned u) {
    unsigned short h = (u & 0x8000) ? (unsigned short)(u ^ 0x8000)
                                    : (unsigned short)~u;
    return __half2float(__ushort_as_half(h));
}

// ---------------- PTX helpers (base PTX only) ---------------------------------
__device__ __forceinline__ uint32_t smem_u32(const void* p) {
    uint32_t a;
    asm("{ .reg .u64 t; cvta.to.shared.u64 t, %1; cvt.u32.u64 %0, t; }"
        : "=r"(a) : "l"(p));
    return a;
}
__device__ __forceinline__ void cpa16(uint32_t dst, const void* src, int sz) {
    asm volatile("cp.async.cg.shared.global [%0], [%1], 16, %2;"
                 :: "r"(dst), "l"(src), "r"(sz));
}
__device__ __forceinline__ void cpcommit() { asm volatile("cp.async.commit_group;"); }
template <int N> __device__ __forceinline__ void cpwait() {
    asm volatile("cp.async.wait_group %0;" :: "n"(N));
}
__device__ __forceinline__ void ldsm4(uint32_t* r, uint32_t addr) {
    asm volatile("ldmatrix.sync.aligned.m8n8.x4.shared.b16 {%0,%1,%2,%3}, [%4];"
                 : "=r"(r[0]), "=r"(r[1]), "=r"(r[2]), "=r"(r[3]) : "r"(addr));
}
__device__ __forceinline__ void mma_bf16(float* d, const uint32_t* a,
                                         uint32_t b0, uint32_t b1) {
    asm volatile(
        "mma.sync.aligned.m16n8k16.row.col.f32.bf16.bf16.f32 "
        "{%0,%1,%2,%3}, {%4,%5,%6,%7}, {%8,%9}, {%0,%1,%2,%3};"
        : "+f"(d[0]), "+f"(d[1]), "+f"(d[2]), "+f"(d[3])
        : "r"(a[0]), "r"(a[1]), "r"(a[2]), "r"(a[3]), "r"(b0), "r"(b1));
}

// ---------------- kernel 1a: centres -> bf16 + c2 -----------------------------
__global__ __launch_bounds__(256) void convertB_kernel(const float* __restrict__ centres) {
    const int warp = (blockIdx.x * 256 + threadIdx.x) >> 5;
    const int lane = threadIdx.x & 31;
    if (warp >= C_) return;
    const float4* src = (const float4*)(centres + (size_t)warp * D_);
    __nv_bfloat16* dst = g_Bbf + (size_t)warp * D_;
    float s = 0.f;
#pragma unroll
    for (int k = 0; k < 4; k++) {
        int j = lane + 32 * k;
        float4 v = src[j];
        s += v.x * v.x + v.y * v.y + v.z * v.z + v.w * v.w;
        union { __nv_bfloat16 h[4]; uint2 u; } ph;
        ph.h[0] = __float2bfloat16_rn(v.x); ph.h[1] = __float2bfloat16_rn(v.y);
        ph.h[2] = __float2bfloat16_rn(v.z); ph.h[3] = __float2bfloat16_rn(v.w);
        *(uint2*)(dst + 4 * j) = ph.u;
    }
#pragma unroll
    for (int o = 16; o; o >>= 1) s += __shfl_xor_sync(0xffffffffu, s, o);
    if (lane == 0) g_c2[warp] = s;
}

// ---------------- kernel 1b: features -> bf16 ---------------------------------
__global__ __launch_bounds__(256) void convertA_kernel(const float* __restrict__ feats) {
    const int warp = (blockIdx.x * 256 + threadIdx.x) >> 5;
    const int lane = threadIdx.x & 31;
    if (warp >= B_) return;
    const float4* src = (const float4*)(feats + (size_t)warp * D_);
    __nv_bfloat16* dst = g_Abf + (size_t)warp * D_;
#pragma unroll
    for (int k = 0; k < 4; k++) {
        int j = lane + 32 * k;
        float4 v = src[j];
        union { __nv_bfloat16 h[4]; uint2 u; } ph;
        ph.h[0] = __float2bfloat16_rn(v.x); ph.h[1] = __float2bfloat16_rn(v.y);
        ph.h[2] = __float2bfloat16_rn(v.z); ph.h[3] = __float2bfloat16_rn(v.w);
        *(uint2*)(dst + 4 * j) = ph.u;
    }
}

// ---------------- kernel 2: bf16 HMMA GEMM, u16 keys + 8-col block minima -----
#define GSTAGE_BYTES 32768
#define GSMEM (1024 + 3 * GSTAGE_BYTES)
__global__ void __launch_bounds__(256, 2) gemm_kernel() {
    extern __shared__ char smem[];
    float* c2s = (float*)smem;
    const uint32_t sb = smem_u32(smem);
    const int t = threadIdx.x;
    const int m0 = blockIdx.x * 128;
    const int c0 = blockIdx.y * 128;
    const int lane = t & 31, wid = t >> 5;
    const int wm = wid & 3, wn = wid >> 2;

    if (t < 128) { int c = c0 + t; c2s[t] = (c < C_) ? g_c2[c] : 0.f; }

    auto load_tile = [&](int kt, int buf) {
        const uint32_t sA = sb + 1024 + buf * GSTAGE_BYTES;
        const uint32_t sB = sA + 16384;
        const __nv_bfloat16* gA = g_Abf + (size_t)m0 * D_ + kt * 64;
        const __nv_bfloat16* gB = g_Bbf + (size_t)c0 * D_ + kt * 64;
#pragma unroll
        for (int i = 0; i < 4; i++) {
            int idx = t + i * 256;
            int r = idx >> 3, c = idx & 7;
            cpa16(sA + r * 128 + ((c ^ (r & 7)) << 4),
                  gA + (size_t)r * D_ + c * 8, 16);
        }
#pragma unroll
        for (int i = 0; i < 4; i++) {
            int idx = t + i * 256;
            int r = idx >> 3, c = idx & 7;
            int gr = c0 + r;
            int sz = (gr < C_) ? 16 : 0;
            const __nv_bfloat16* src = gB + (size_t)((gr < C_) ? r : 0) * D_ + c * 8;
            cpa16(sB + r * 128 + ((c ^ (r & 7)) << 4), src, sz);
        }
        cpcommit();
    };

    float acc[2][8][4];
#pragma unroll
    for (int i = 0; i < 2; i++)
#pragma unroll
        for (int j = 0; j < 8; j++)
#pragma unroll
            for (int q = 0; q < 4; q++) acc[i][j][q] = 0.f;

    load_tile(0, 0);
    load_tile(1, 1);

#pragma unroll 1
    for (int kt = 0; kt < 8; kt++) {
        const int buf = kt % 3;
        if (kt == 7) cpwait<0>(); else cpwait<1>();
        __syncthreads();
        if (kt + 2 < 8) load_tile(kt + 2, (kt + 2) % 3);
        const uint32_t sA = sb + 1024 + buf * GSTAGE_BYTES;
        const uint32_t sB = sA + 16384;
#pragma unroll
        for (int kk = 0; kk < 4; kk++) {
            uint32_t a[2][4], b[4][4];
#pragma unroll
            for (int mt = 0; mt < 2; mt++) {
                int r = wm * 32 + mt * 16 + (lane & 15);
                int ch = kk * 2 + (lane >> 4);
                ldsm4(a[mt], sA + r * 128 + ((ch ^ (r & 7)) << 4));
            }
#pragma unroll
            for (int nt = 0; nt < 4; nt++) {
                int r = wn * 64 + nt * 16 + ((lane >> 4) << 3) + (lane & 7);
                int ch = kk * 2 + ((lane >> 3) & 1);
                ldsm4(b[nt], sB + r * 128 + ((ch ^ (r & 7)) << 4));
            }
#pragma unroll
            for (int mt = 0; mt < 2; mt++)
#pragma unroll
                for (int nt = 0; nt < 4; nt++) {
                    mma_bf16(acc[mt][nt * 2],     a[mt], b[nt][0], b[nt][1]);
                    mma_bf16(acc[mt][nt * 2 + 1], a[mt], b[nt][2], b[nt][3]);
                }
        }
    }

    // epilogue: u16 ordered keys + per-8-col block minima.
    // For each (mt, nt8): the 4 lanes of a quad cover exactly one 8-col block
    // for rows grow and grow+8. C_ % 8 == 0 -> gcol guard is warp-uniform.
#pragma unroll
    for (int mt = 0; mt < 2; mt++) {
#pragma unroll
        for (int nt8 = 0; nt8 < 8; nt8++) {
            int lcol = wn * 64 + nt8 * 8 + (lane & 3) * 2;
            int gcol = c0 + lcol;
            if (gcol >= C_) continue;
            int grow = m0 + wm * 32 + mt * 16 + (lane >> 2);
            float a0 = c2s[lcol]     - 2.f * acc[mt][nt8][0];
            float a1 = c2s[lcol + 1] - 2.f * acc[mt][nt8][1];
            float a2 = c2s[lcol]     - 2.f * acc[mt][nt8][2];
            float a3 = c2s[lcol + 1] - 2.f * acc[mt][nt8][3];
            unsigned k0 = f2ord16(a0), k1 = f2ord16(a1);
            unsigned k2 = f2ord16(a2), k3 = f2ord16(a3);
            *(unsigned*)(g_keys16 + (size_t)grow * C_ + gcol)       = k0 | (k1 << 16);
            *(unsigned*)(g_keys16 + (size_t)(grow + 8) * C_ + gcol) = k2 | (k3 << 16);
            // block minima across the quad (shuffles warp-uniform here)
            float m01 = fminf(a0, a1);
            float m23 = fminf(a2, a3);
            m01 = fminf(m01, __shfl_xor_sync(0xffffffffu, m01, 1));
            m01 = fminf(m01, __shfl_xor_sync(0xffffffffu, m01, 2));
            m23 = fminf(m23, __shfl_xor_sync(0xffffffffu, m23, 1));
            m23 = fminf(m23, __shfl_xor_sync(0xffffffffu, m23, 2));
            if ((lane & 3) == 0) {
                int blk = (c0 >> 3) + wn * 8 + nt8;
                g_bmin[(size_t)grow * NBLK + blk]       = (unsigned short)f2ord16(m01);
                g_bmin[(size_t)(grow + 8) * NBLK + blk] = (unsigned short)f2ord16(m23);
            }
        }
    }
}

// ---------------- kernel 3: bmin radix threshold + hierarchical collect ------
__global__ __launch_bounds__(256) void select_kernel() {
    const int row = blockIdx.x;
    const unsigned short* bmin = g_bmin + (size_t)row * NBLK;
    __shared__ unsigned whist[8][256];   // per-warp histograms (plain atomics)
    __shared__ unsigned hist[256];
    __shared__ unsigned sh_b1, sh_base, sh_T;
    __shared__ int sh_ncand;
    const int t = threadIdx.x;
    const int warp = t >> 5;

    if (t == 0) sh_ncand = 0;
#pragma unroll
    for (int w = 0; w < 8; w++) whist[w][t & 255] = 0;
    __syncthreads();

    // pass A1: histogram of bmin high byte
    for (int i = t; i < NBLK; i += 256)
        atomicAdd(&whist[warp][bmin[i] >> 8], 1u);
    __syncthreads();
    {
        unsigned s = 0;
#pragma unroll
        for (int w = 0; w < 8; w++) s += whist[w][t];
        hist[t] = s;
    }
    __syncthreads();
    if (t == 0) {
        unsigned cum = 0;
        int b = 0;
        for (; b < 255; b++) {
            if (cum + hist[b] >= (unsigned)RANK) break;
            cum += hist[b];
        }
        sh_b1 = (unsigned)b;
        sh_base = cum;
    }
    __syncthreads();
#pragma unroll
    for (int w = 0; w < 8; w++) whist[w][t] = 0;
    __syncthreads();

    // pass A2: low-byte histogram among bmins with high byte == b1
    const unsigned b1 = sh_b1;
    for (int i = t; i < NBLK; i += 256) {
        unsigned v = bmin[i];
        if ((v >> 8) == b1) atomicAdd(&whist[warp][v & 255u], 1u);
    }
    __syncthreads();
    {
        unsigned s = 0;
#pragma unroll
        for (int w = 0; w < 8; w++) s += whist[w][t];
        hist[t] = s;
    }
    __syncthreads();
    if (t == 0) {
        unsigned cum = sh_base;
        int b = 0;
        for (; b < 255; b++) {
            if (cum + hist[b] >= (unsigned)RANK) break;
            cum += hist[b];
        }
        unsigned T0 = (b1 << 8) | (unsigned)b;        // rank-RANK bmin
        unsigned Tm = f2ord16(ord162f(T0) + MARGIN) + 1;
        if (Tm > 65535u) Tm = 65535u;
        sh_T = (Tm > T0) ? Tm : T0;
    }
    __syncthreads();

    // pass B: expand hit blocks only
    const unsigned T = sh_T;
    int* cand = g_cand + (size_t)row * CCAP;
    const unsigned short* keys = g_keys16 + (size_t)row * C_;
    for (int i = t; i < NBLK; i += 256) {
        if (bmin[i] <= T) {
            uint4 v = *(const uint4*)(keys + i * 8);
            unsigned w[4] = {v.x, v.y, v.z, v.w};
            int col = i * 8;
#pragma unroll
            for (int q = 0; q < 4; q++) {
                if ((w[q] & 0xFFFFu) <= T) {
                    int pos = atomicAdd(&sh_ncand, 1);
                    if (pos < CCAP) cand[pos] = col + q * 2;
                }
                if ((w[q] >> 16) <= T) {
                    int pos = atomicAdd(&sh_ncand, 1);
                    if (pos < CCAP) cand[pos] = col + q * 2 + 1;
                }
            }
        }
    }
    __syncthreads();
    if (t == 0) g_ccnt[row] = min(sh_ncand, CCAP);
}

// ---------------- kernel 4: exact rescore + top-200 + histogram + log --------
__global__ __launch_bounds__(256) void rescore_kernel(const float* __restrict__ features,
                                                      const float* __restrict__ centres,
                                                      const int*   __restrict__ labels,
                                                      const float* __restrict__ weight,
                                                      float* __restrict__ out) {
    const int row = blockIdx.x;
    __shared__ float f[D_];
    __shared__ float p[NCLS];
    __shared__ unsigned long long cnd[CCAP];
    __shared__ float red[8];
    const int t = threadIdx.x;
    const int warp = t >> 5, lane = t & 31;

    for (int i = t; i < D_; i += 256) f[i] = features[(size_t)row * D_ + i];
    for (int i = t; i < NCLS; i += 256) p[i] = 0.f;
    __syncthreads();

    const int cnt = g_ccnt[row];
    const int* cand = g_cand + (size_t)row * CCAP;

    for (int ci = warp; ci < cnt; ci += 8) {
        int idx = cand[ci];
        const float4* c = (const float4*)(centres + (size_t)idx * D_);
        const float4* fs = (const float4*)f;
        float s = 0.f;
#pragma unroll
        for (int k = 0; k < 4; k++) {
            int j = lane + 32 * k;
            float4 cv = c[j];
            float4 fv = fs[j];
            float dx = fv.x - cv.x, dy = fv.y - cv.y;
            float dz = fv.z - cv.z, dw = fv.w - cv.w;
            s += dx * dx + dy * dy + dz * dz + dw * dw;
        }
#pragma unroll
        for (int o = 16; o; o >>= 1) s += __shfl_xor_sync(0xffffffffu, s, o);
        if (lane == 0)
            cnd[ci] = ((unsigned long long)f2ord(s) << 32) | (unsigned)idx;
    }
    __syncthreads();

    int P = 256;
    while (P < cnt) P <<= 1;
    for (int i = cnt + t; i < P; i += 256) cnd[i] = ~0ull;
    __syncthreads();
    for (int k = 2; k <= P; k <<= 1)
        for (int j = k >> 1; j > 0; j >>= 1) {
            for (int i = t; i < P; i += 256) {
                int ixj = i ^ j;
                if (ixj > i) {
                    unsigned long long a = cnd[i], b = cnd[ixj];
                    bool up = ((i & k) == 0);
                    if ((a > b) == up) { cnd[i] = b; cnd[ixj] = a; }
                }
            }
            __syncthreads();
        }

    const int take = min(KNN, cnt);
    for (int s = t; s < take; s += 256) {
        unsigned long long v = cnd[s];
        int idx = (int)(v & 0xffffffffull);
        float d2 = ord2f((unsigned)(v >> 32));
        float d = expf(-d2 * GCONST) * expf(weight[idx]);
        atomicAdd(&p[labels[idx]], d);
    }
    __syncthreads();

    float partial = 0.f;
    for (int i = t; i < NCLS; i += 256) {
        float v = p[i];
        if (v == 0.f) v = 1e-10f;
        p[i] = v;
        partial += v;
    }
#pragma unroll
    for (int o = 16; o; o >>= 1) partial += __shfl_xor_sync(0xffffffffu, partial, o);
    if (lane == 0) red[warp] = partial;
    __syncthreads();
    if (t < 32) {
        float v = (t < 8) ? red[t] : 0.f;
#pragma unroll
        for (int o = 4; o; o >>= 1) v += __shfl_xor_sync(0xffffffffu, v, o);
        if (t == 0) red[0] = v;
    }
    __syncthreads();
    const float sum = red[0];
    for (int i = t; i < NCLS; i += 256)
        out[(size_t)row * NCLS + i] = logf(p[i] / sum);
}

// ---------------- launcher ----------------------------------------------------
extern "C" void kernel_launch(void* const* d_in, const int* in_sizes, int n_in,
                              void* d_out, int out_size) {
    const float* features = (const float*)d_in[0];   // [512, 512]
    const float* centres  = (const float*)d_in[1];   // [100000, 512]
    const int*   labels   = (const int*)d_in[2];     // [100000]
    const float* weight   = (const float*)d_in[3];   // [100000]
    float* out = (float*)d_out;                      // [512, 1000]

    cudaFuncSetAttribute(gemm_kernel,
                         cudaFuncAttributeMaxDynamicSharedMemorySize, GSMEM);

    convertA_kernel<<<B_ / 8, 256>>>(features);
    convertB_kernel<<<C_ / 8, 256>>>(centres);

    dim3 gg(B_ / 128, (C_ + 127) / 128);   // x = m-tile (fast), y = c-tile
    gemm_kernel<<<gg, 256, GSMEM>>>();

    select_kernel<<<B_, 256>>>();

    rescore_kernel<<<B_, 256>>>(features, centres, labels, weight, out);
}